// round 10
// baseline (speedup 1.0000x reference)
#include <cuda_runtime.h>
#include <cuda_bf16.h>

#define BATCH 32
#define NAG   6
#define KS    256
#define QS    256
#define CHW   (512*32*32)       /* 524288 floats per (b,n) slab */
#define V4PB  (CHW/4)           /* 131072 float4 per (b,n) slab */
#define CHUNKS 8                /* attn kk-chunks per batch (32 rows each) */
#define TILES 2048              /* wsum tiles: 2048 float4 each */
#define GRID  1024              /* 2 tiles per block */

// Scratch (allocation-free rule: __device__ globals). All counters are reset
// inside the kernel so every graph replay starts from identical state.
__device__ float        g_attn[BATCH * NAG];
__device__ float        g_score[BATCH * NAG];
__device__ unsigned int g_cnt[BATCH];
__device__ unsigned int g_ready;     // # batches finalized (0..32)
__device__ unsigned int g_fin;       // # blocks finished (0..GRID)

// ---------------------------------------------------------------------------
// Persistent fused kernel, grid = 1024 x 256, min 6 blocks/SM.
//  * blocks 0..255 first run one attn chunk: query rows via warp dots ->
//    partial agent scores -> ticketed sparsemax -> g_attn -> g_ready++.
//  * all blocks: wait g_ready==32, stage all 192 weights, then 2 tiles each:
//      copy phase : out = w[n0] * v[n0]      (first nonzero agent, MLP=8)
//      rare phase : out += w[n] * v[n]       (additional agents, RMW, low reg)
//    Sparsemax guarantees sum(w)=1 so at least one agent is nonzero.
//  * last finishing block resets g_ready/g_fin for the next graph replay.
// ---------------------------------------------------------------------------
__global__ void __launch_bounds__(256, 6)
fused_kernel(const float* __restrict__ q,
             const float* __restrict__ k,
             const float* __restrict__ v,
             const float* __restrict__ W,
             const float* __restrict__ bias,
             float* __restrict__ out,
             float* __restrict__ out_attn,
             int write_attn) {
    const int bid  = blockIdx.x;
    const int t    = threadIdx.x;
    const int wid  = t >> 5, lane = t & 31;

    __shared__ float4 sq4[QS / 4];
    __shared__ float  squery[32];
    __shared__ float  sw[BATCH * NAG];   // all weights, staged once
    __shared__ int    sfirst[BATCH];     // first nonzero agent per batch

    // ================= attn phase (blocks 0..255 only) ====================
    if (bid < BATCH * CHUNKS) {
        const int ab     = bid >> 3;
        const int kkbase = (bid & 7) << 5;

        if (t < QS / 4) sq4[t] = ((const float4*)(q + ab * QS))[t];
        __syncthreads();

        // warp `wid` computes 4 query rows, 2 at a time
        {
            const int r0 = kkbase + (wid << 2);
            const float4 q0 = sq4[lane], q1 = sq4[lane + 32];
            #pragma unroll
            for (int h = 0; h < 2; h++) {
                const int ra = r0 + 2 * h;
                const float4* wa = (const float4*)(W + ra * QS);
                const float4* wb = (const float4*)(W + (ra + 1) * QS);
                float4 a0 = wa[lane], a1 = wa[lane + 32];
                float4 b0 = wb[lane], b1 = wb[lane + 32];
                float sa = a0.x * q0.x + a0.y * q0.y + a0.z * q0.z + a0.w * q0.w
                         + a1.x * q1.x + a1.y * q1.y + a1.z * q1.z + a1.w * q1.w;
                float sb = b0.x * q0.x + b0.y * q0.y + b0.z * q0.z + b0.w * q0.w
                         + b1.x * q1.x + b1.y * q1.y + b1.z * q1.z + b1.w * q1.w;
                #pragma unroll
                for (int o = 16; o; o >>= 1) {
                    sa += __shfl_xor_sync(0xffffffffu, sa, o);
                    sb += __shfl_xor_sync(0xffffffffu, sb, o);
                }
                if (lane == 0) {
                    squery[(wid << 2) + 2 * h]     = sa + bias[ra];
                    squery[(wid << 2) + 2 * h + 1] = sb + bias[ra + 1];
                }
            }
        }
        __syncthreads();

        // 6 warps -> partial agent scores
        if (wid < NAG) {
            float p = k[(ab * NAG + wid) * KS + kkbase + lane] * squery[lane];
            #pragma unroll
            for (int o = 16; o; o >>= 1) p += __shfl_xor_sync(0xffffffffu, p, o);
            if (lane == 0) atomicAdd(&g_score[ab * NAG + wid], p);
        }

        __threadfence();
        if (t == 0 && atomicAdd(&g_cnt[ab], 1u) == CHUNKS - 1) {
            __threadfence();                      // acquire all partials
            float z[NAG], zs[NAG];
            #pragma unroll
            for (int n = 0; n < NAG; n++) {
                z[n] = g_score[ab * NAG + n];
                zs[n] = z[n];
                g_score[ab * NAG + n] = 0.0f;     // reset for next replay
            }
            g_cnt[ab] = 0u;
            #pragma unroll
            for (int i = 1; i < NAG; i++) {       // insertion sort, descending
                float key = zs[i]; int j = i - 1;
                while (j >= 0 && zs[j] < key) { zs[j + 1] = zs[j]; j--; }
                zs[j + 1] = key;
            }
            float cs[NAG], run = 0.f;
            #pragma unroll
            for (int r = 0; r < NAG; r++) { run += zs[r]; cs[r] = run; }
            int kk = 0;
            #pragma unroll
            for (int r = 1; r <= NAG; r++)
                if (1.0f + (float)r * zs[r - 1] > cs[r - 1]) kk++;
            const float tau = (cs[kk - 1] - 1.0f) / (float)kk;
            #pragma unroll
            for (int n = 0; n < NAG; n++) {
                float p = fmaxf(z[n] - tau, 0.0f);
                g_attn[ab * NAG + n] = p;
                if (write_attn) out_attn[ab * NAG + n] = p;
            }
            __threadfence();                      // publish before counting
            atomicAdd(&g_ready, 1u);
        }
        __syncthreads();
    }

    // ================= wait once, stage weights ===========================
    if (t == 0) {
        while (*((volatile unsigned int*)&g_ready) != BATCH) __nanosleep(64);
    }
    __syncthreads();
    if (t < BATCH * NAG) sw[t] = __ldcg(&g_attn[t]);
    __syncthreads();
    if (t < BATCH) {
        int n0 = 0;
        while (n0 < NAG - 1 && sw[t * NAG + n0] == 0.0f) n0++;
        sfirst[t] = n0;
    }
    __syncthreads();

    // ================= persistent wsum loop (2 tiles/block) ===============
    for (int tau = bid; tau < TILES; tau += GRID) {
        const int b    = tau >> 6;                        // 64 tiles/batch
        const int base = ((tau & 63) << 11) + t;          // float4 idx in slab

        const float4* vb = (const float4*)v + (b * (NAG * V4PB) + base);
        float4*       ob = (float4*)out    + (b * V4PB + base);

        // ---- copy phase: first nonzero agent, 8 loads in flight ----------
        const int n0 = sfirst[b];
        {
            const float w = sw[b * NAG + n0];
            const float4* p = vb + n0 * V4PB;
            float4 x[8];
            #pragma unroll
            for (int i = 0; i < 8; i++) x[i] = __ldcs(p + (i << 8));
            #pragma unroll
            for (int i = 0; i < 8; i++) {
                float4 r;
                r.x = w * x[i].x; r.y = w * x[i].y;
                r.z = w * x[i].z; r.w = w * x[i].w;
                __stcs(ob + (i << 8), r);
            }
        }

        // ---- rare phase: additional nonzero agents, elementwise RMW ------
        for (int n = n0 + 1; n < NAG; n++) {
            const float w = sw[b * NAG + n];
            if (w != 0.0f) {                      // block-uniform branch
                const float4* p = vb + n * V4PB;
                float4 x[8];
                #pragma unroll
                for (int i = 0; i < 8; i++) x[i] = __ldcs(p + (i << 8));
                #pragma unroll
                for (int i = 0; i < 8; i++) {
                    float4 o = ob[i << 8];
                    o.x = fmaf(w, x[i].x, o.x); o.y = fmaf(w, x[i].y, o.y);
                    o.z = fmaf(w, x[i].z, o.z); o.w = fmaf(w, x[i].w, o.w);
                    __stcs(ob + (i << 8), o);
                }
            }
        }
    }

    // -------- reset the global counters for the next graph replay ---------
    __syncthreads();
    if (t == 0 && atomicAdd(&g_fin, 1u) == GRID - 1) {
        g_fin = 0u;
        g_ready = 0u;
    }
}

// ---------------------------------------------------------------------------
extern "C" void kernel_launch(void* const* d_in, const int* in_sizes, int n_in,
                              void* d_out, int out_size) {
    const float* q    = (const float*)d_in[0];
    const float* k    = (const float*)d_in[1];
    const float* v    = (const float*)d_in[2];
    const float* W    = (const float*)d_in[3];
    const float* bias = (const float*)d_in[4];

    float* out = (float*)d_out;
    const long long out_main = (long long)BATCH * CHW;        // 16777216
    const int write_attn = (out_size >= out_main + BATCH * NAG) ? 1 : 0;
    float* out_attn = out + out_main;

    fused_kernel<<<GRID, 256>>>(q, k, v, W, bias, out, out_attn, write_attn);
}